// round 9
// baseline (speedup 1.0000x reference)
#include <cuda_runtime.h>
#include <mma.h>
#include <math.h>
#include <stdint.h>

using namespace nvcuda;

// ===========================================================================
// AdaptiveFeaturePropagation, round 9: wmma tf32 + cp.async double-buffering.
// R7 showed tensor pipe at 9.9% active / issue 6.3% -> stall-bound, not HW
// ceiling. This round: producers pre-round to tf32 (staging = raw bytes),
// cp.async double-buffered K-chunks of 16, static 37KB smem, 2 CTAs/SM.
// 3x3 convs = 9 shifted 1x1 GEMMs over statically-zero padded planes.
// ===========================================================================

static constexpr int HH = 129, WW = 129, HWP = HH * WW;   // 16641
static constexpr int PH = 131;                            // padded row width
static constexpr int PHW = PH * PH;                       // 17161
static constexpr int PLANE = 17568;                       // padded plane + guards
static constexpr int GUARD = 132;                         // lead guard
static constexpr int MT = 135;                            // ceil(17161/128)

__device__ float g_up_pad [4 * 128 * PLANE];  // padded upsampled (tf32-rounded)
__device__ float g_red_pad[2 * 512 * PLANE];  // padded relu(conv1) (tf32-rounded)
__device__ float g_c2  [2 * 256 * HWP];       // relu(conv2), fp32
__device__ float g_kern[2 * 49  * HWP];       // softmax kernels
__device__ float g_w1T [9 * 256 * 128];       // w_reduce [tap][oc][ci], tf32
__device__ float g_w2T [9 * 256 * 512];       // w_conv2  [tap][oc][ci], tf32

__device__ __forceinline__ float f2tf32(float v) {
    float r;
    asm("cvt.rna.tf32.f32 %0, %1;" : "=f"(r) : "f"(v));
    return r;
}
__device__ __forceinline__ void cpa4(uint32_t dst, const float* src) {
    asm volatile("cp.async.ca.shared.global [%0], [%1], 4;"
                 :: "r"(dst), "l"(src) : "memory");
}
__device__ __forceinline__ void cpa16(uint32_t dst, const float* src) {
    asm volatile("cp.async.cg.shared.global [%0], [%1], 16;"
                 :: "r"(dst), "l"(src) : "memory");
}
__device__ __forceinline__ void cpa_commit() {
    asm volatile("cp.async.commit_group;" ::: "memory");
}
template<int N>
__device__ __forceinline__ void cpa_wait() {
    asm volatile("cp.async.wait_group %0;" :: "n"(N) : "memory");
}

// ---------------------------------------------------------------------------
// 1) Bilinear upsample into padded layout, output rounded to tf32
// ---------------------------------------------------------------------------
__global__ __launch_bounds__(256)
void upsample_kernel(const float* __restrict__ cur, const float* __restrict__ key)
{
    int idx = blockIdx.x * 256 + threadIdx.x;
    if (idx >= 4 * 128 * HWP) return;
    int slot = idx / (128 * HWP);
    int rem  = idx - slot * (128 * HWP);
    int c    = rem / HWP;
    int p    = rem - c * HWP;
    int Y = p / WW, X = p - Y * WW;
    int frame = slot & 1, b = slot >> 1;
    const float* src = (frame ? key : cur) + (b * 128 + c) * (33 * 33);

    const float s = 33.0f / 129.0f;
    float fy = (Y + 0.5f) * s - 0.5f;
    float fx = (X + 0.5f) * s - 0.5f;
    float y0f = floorf(fy), x0f = floorf(fx);
    float wy = fy - y0f, wx = fx - x0f;
    int y0 = (int)y0f, x0 = (int)x0f;
    int y0c = max(y0, 0), y1c = min(y0 + 1, 32);
    int x0c = max(x0, 0), x1c = min(x0 + 1, 32);

    float v00 = src[y0c * 33 + x0c], v01 = src[y0c * 33 + x1c];
    float v10 = src[y1c * 33 + x0c], v11 = src[y1c * 33 + x1c];
    float v0 = v00 + (v01 - v00) * wx;
    float v1 = v10 + (v11 - v10) * wx;
    g_up_pad[(size_t)slot * (128 * PLANE) + (size_t)c * PLANE
             + GUARD + (Y + 1) * PH + (X + 1)] = f2tf32(v0 + (v1 - v0) * wy);
}

// ---------------------------------------------------------------------------
// Weight transpose + tf32 rounding: wT[tap][oc][ci] = tf32(w[oc][ci][tap])
// ---------------------------------------------------------------------------
__global__ __launch_bounds__(256)
void transpose_w_kernel(const float* __restrict__ w, float* __restrict__ wT, int CIN)
{
    int i = blockIdx.x * 256 + threadIdx.x;
    int total = 9 * 256 * CIN;
    if (i >= total) return;
    int tap = i / (256 * CIN);
    int rem = i - tap * (256 * CIN);
    int n   = rem / CIN;
    int ci  = rem - n * CIN;
    wT[i] = f2tf32(w[(n * CIN + ci) * 9 + tap]);
}

// ---------------------------------------------------------------------------
// 2/3) 3x3 conv via wmma tf32 m16n16k8, cp.async double-buffered.
//   CTA: M=128 pixels x N=128 ocs; 8 warps 2(M)x4(N); warp 64x32 = 4x2 frags.
//   K-chunk 16 (2 k-steps), iterated over 9 taps x CIN/16 chunks.
//   A smem [k][m] (col-major, ldm 132); B smem [n][k] (col-major, ldm 20).
//   MODE 0: g_up_pad -> g_red_pad (padded, relu, tf32-rounded)
//   MODE 1: g_red_pad -> g_c2 (unpadded, relu, fp32)
// ---------------------------------------------------------------------------
static constexpr int ALD = 132;  // A ldm
static constexpr int BLD = 20;   // B ldm
static constexpr int BST = 36;   // epilogue buffer stride

template<int CIN, int MODE>
__global__ __launch_bounds__(256, 2)
void conv_mma(const float* __restrict__ wT, const float* __restrict__ bias)
{
    constexpr int KC    = CIN / 16;
    constexpr int TOTAL = 9 * KC;

    __shared__ __align__(16) float sA[2][16][ALD];   // 16.9 KB
    __shared__ __align__(16) float sB[2][128][BLD];  // 20.5 KB

    const int tid = threadIdx.x;
    const int wid = tid >> 5;
    const int wm  = wid & 1;
    const int wn  = wid >> 1;
    const int Lbase = blockIdx.x * 128;
    const int n0    = blockIdx.y * 128;

    const float* in = (MODE == 0)
        ? (g_up_pad  + (size_t)blockIdx.z * (128 * PLANE))
        : (g_red_pad + (size_t)blockIdx.z * (512 * PLANE));

    const uint32_t saBase = (uint32_t)__cvta_generic_to_shared(&sA[0][0][0]);
    const uint32_t sbBase = (uint32_t)__cvta_generic_to_shared(&sB[0][0][0]);

    // staging maps (fixed per thread)
    const int a_k = tid >> 7;            // +2*r gives k 0..15 over 8 ops
    const int a_m = tid & 127;
    const int b_n = tid >> 2;            // +64*r gives n 0..127 over 2 ops
    const int b_k = (tid & 3) * 4;

    wmma::fragment<wmma::accumulator, 16, 16, 8, float> cf[4][2];
#pragma unroll
    for (int i = 0; i < 4; i++)
#pragma unroll
        for (int j = 0; j < 2; j++) wmma::fill_fragment(cf[i][j], 0.f);

    // ---- stage helper (inlined twice) ----
    auto stage = [&](int it, int buf) {
        const int tap   = it / KC;
        const int chunk = it - tap * KC;
        const int c0    = chunk * 16;
        const int off   = (tap / 3 - 1) * PH + (tap % 3 - 1);
        const float* ag = in + GUARD + Lbase + off;
#pragma unroll
        for (int r = 0; r < 8; ++r) {
            const int k = a_k + r * 2;
            cpa4(saBase + (uint32_t)(((buf * 16 + k) * ALD + a_m) * 4),
                 ag + (size_t)(c0 + k) * PLANE + a_m);
        }
        const float* bg = wT + ((size_t)tap * 256 + n0) * CIN + c0;
#pragma unroll
        for (int r = 0; r < 2; ++r) {
            const int n = b_n + r * 64;
            cpa16(sbBase + (uint32_t)(((buf * 128 + n) * BLD + b_k) * 4),
                  bg + (size_t)n * CIN + b_k);
        }
        cpa_commit();
    };

    stage(0, 0);

    for (int it = 0; it < TOTAL; ++it) {
        const int buf = it & 1;
        if (it + 1 < TOTAL) {
            stage(it + 1, buf ^ 1);
            cpa_wait<1>();
        } else {
            cpa_wait<0>();
        }
        __syncthreads();

#pragma unroll
        for (int ks = 0; ks < 2; ++ks) {
            wmma::fragment<wmma::matrix_a, 16, 16, 8, wmma::precision::tf32,
                           wmma::col_major> af[4];
            wmma::fragment<wmma::matrix_b, 16, 16, 8, wmma::precision::tf32,
                           wmma::col_major> bf[2];
#pragma unroll
            for (int i = 0; i < 4; ++i)
                wmma::load_matrix_sync(af[i], &sA[buf][ks * 8][wm * 64 + i * 16], ALD);
#pragma unroll
            for (int j = 0; j < 2; ++j)
                wmma::load_matrix_sync(bf[j], &sB[buf][wn * 32 + j * 16][ks * 8], BLD);
#pragma unroll
            for (int i = 0; i < 4; ++i)
#pragma unroll
                for (int j = 0; j < 2; ++j)
                    wmma::mma_sync(cf[i][j], af[i], bf[j], cf[i][j]);
        }
        __syncthreads();   // protect buf before it is re-staged next iter
    }

    // ---- epilogue: per N-group via smem buffer; bias + relu; bounds ----
    float* buf = &sB[0][0][0];   // 128 x 36 = 18.4 KB <= sB (20.5 KB)
    for (int g = 0; g < 4; ++g) {
        __syncthreads();
        if (wn == g) {
#pragma unroll
            for (int i = 0; i < 4; ++i)
#pragma unroll
                for (int j = 0; j < 2; ++j)
                    wmma::store_matrix_sync(&buf[(wm * 64 + i * 16) * BST + j * 16],
                                            cf[i][j], BST, wmma::mem_row_major);
        }
        __syncthreads();
#pragma unroll
        for (int i = 0; i < 16; ++i) {
            int e  = tid + i * 256;        // 0..4095
            int m  = e & 127;
            int nl = e >> 7;               // 0..31
            int L  = Lbase + m;
            int r  = L / PH, c = L - r * PH;
            bool valid = (L < PHW) && (r >= 1) && (r <= HH) && (c >= 1) && (c <= WW);
            if (!valid) continue;
            int n = n0 + g * 32 + nl;
            float v = fmaxf(buf[m * BST + nl] + __ldg(bias + n), 0.f);
            if (MODE == 0)
                g_red_pad[((size_t)blockIdx.z * 256 + n) * PLANE + GUARD + L]
                    = f2tf32(v);
            else
                g_c2[((size_t)blockIdx.z * 256 + n) * HWP + (r - 1) * WW + (c - 1)] = v;
        }
    }
}

// ---------------------------------------------------------------------------
// 4) conv3 (1x1, 256->49) + bias + relu + softmax (proven R5 version)
// ---------------------------------------------------------------------------
__global__ __launch_bounds__(256)
void conv3_softmax_kernel(const float* __restrict__ w3, const float* __restrict__ b3)
{
    __shared__ float sw[49 * 128];
    int g = blockIdx.x * 256 + threadIdx.x;
    bool valid = g < 2 * HWP;
    int b = 0, p = 0;
    if (valid) { b = g / HWP; p = g - b * HWP; }

    float acc[49];
#pragma unroll
    for (int t = 0; t < 49; t++) acc[t] = 0.f;

    for (int h = 0; h < 2; h++) {
        __syncthreads();
        for (int e = threadIdx.x; e < 49 * 128; e += 256)
            sw[e] = w3[(e >> 7) * 256 + h * 128 + (e & 127)];
        __syncthreads();
        if (valid) {
            const float* xc = g_c2 + (size_t)b * (256 * HWP) + (size_t)h * 128 * HWP + p;
            for (int cl = 0; cl < 128; cl++) {
                float xv = __ldg(xc + cl * HWP);
#pragma unroll
                for (int t = 0; t < 49; t++)
                    acc[t] += xv * sw[t * 128 + cl];
            }
        }
    }
    if (!valid) return;

    float mx = -1e30f;
#pragma unroll
    for (int t = 0; t < 49; t++) {
        acc[t] = fmaxf(acc[t] + b3[t], 0.f);
        mx = fmaxf(mx, acc[t]);
    }
    float s = 0.f;
#pragma unroll
    for (int t = 0; t < 49; t++) { acc[t] = expf(acc[t] - mx); s += acc[t]; }
    float inv = 1.f / s;
#pragma unroll
    for (int t = 0; t < 49; t++)
        g_kern[((size_t)b * 49 + t) * HWP + p] = acc[t] * inv;
}

// ---------------------------------------------------------------------------
// 5) Spatially-variant 7x7 conv (proven R5 version)
// ---------------------------------------------------------------------------
__global__ __launch_bounds__(256)
void svc_kernel(const float* __restrict__ feat, float* __restrict__ out)
{
    __shared__ float sk[49][128];
    const int x0 = blockIdx.x * 16, y0 = blockIdx.y * 8, b = blockIdx.z;
    const int tid = threadIdx.x;

    for (int e = tid; e < 49 * 128; e += 256) {
        int t = e >> 7, pix = e & 127;
        int yy = y0 + (pix >> 4), xx = x0 + (pix & 15);
        float v = 0.f;
        if (yy < HH && xx < WW) v = g_kern[((size_t)b * 49 + t) * HWP + yy * WW + xx];
        sk[t][pix] = v;
    }
    __syncthreads();

    const int half = tid >> 7;
    const int pix  = tid & 127;
    const int y = y0 + (pix >> 4);
    const int x = x0 + (pix & 15);
    const bool valid = (y < HH) && (x < WW);
    const float* fb = feat + (size_t)b * 256 * HWP;

    for (int c = half; c < 256; c += 2) {
        const float* fc = fb + (size_t)c * HWP;
        float acc = 0.f;
#pragma unroll
        for (int i = 0; i < 7; i++) {
            int yy = y + i - 3;
            if ((unsigned)yy < (unsigned)HH) {
#pragma unroll
                for (int j = 0; j < 7; j++) {
                    int xx = x + j - 3;
                    if ((unsigned)xx < (unsigned)WW)
                        acc += sk[i * 7 + j][pix] * __ldg(fc + yy * WW + xx);
                }
            }
        }
        if (valid) out[((size_t)b * 256 + c) * HWP + y * WW + x] = acc;
    }
}

// ---------------------------------------------------------------------------
// Launcher (graph-capturable: kernel launches only)
// ---------------------------------------------------------------------------
extern "C" void kernel_launch(void* const* d_in, const int* in_sizes, int n_in,
                              void* d_out, int out_size)
{
    const float* cur = (const float*)d_in[0];
    const float* key = (const float*)d_in[1];
    const float* hi  = (const float*)d_in[2];
    const float* w1  = (const float*)d_in[3];
    const float* b1  = (const float*)d_in[4];
    const float* w2  = (const float*)d_in[5];
    const float* b2  = (const float*)d_in[6];
    const float* w3  = (const float*)d_in[7];
    const float* b3  = (const float*)d_in[8];
    float* out = (float*)d_out;

    // weight transposes (tiny, tf32-rounded) + padded upsample (tf32-rounded)
    transpose_w_kernel<<<(9 * 256 * 128 + 255) / 256, 256>>>(w1, g_w1T, 128);
    transpose_w_kernel<<<(9 * 256 * 512 + 255) / 256, 256>>>(w2, g_w2T, 512);
    upsample_kernel<<<(4 * 128 * HWP + 255) / 256, 256>>>(cur, key);

    // conv_reduce: 4 image slots -> padded concat layout (relu fused)
    conv_mma<128, 0><<<dim3(MT, 2, 4), 256>>>(g_w1T, b1);

    // conv2: per batch (relu fused)
    conv_mma<512, 1><<<dim3(MT, 2, 2), 256>>>(g_w2T, b2);

    // conv3 + relu + softmax
    conv3_softmax_kernel<<<(2 * HWP + 255) / 256, 256>>>(w3, b3);

    // spatially-variant 7x7 conv
    svc_kernel<<<dim3(9, 17, 2), 256>>>(hi, out);
}

// round 10
// speedup vs baseline: 2.2757x; 2.2757x over previous
#include <cuda_runtime.h>
#include <math.h>
#include <stdint.h>

// ===========================================================================
// AdaptiveFeaturePropagation, round 10: max-efficiency SIMT fp32 SGEMM convs.
// Tensor paths measured: wmma tf32 14.9 TF/s (R7), cp.async variant 6 TF/s
// (R9), f32x2 14 TF/s (R8) -- all below plain FFMA's 23.6 TF/s (R5).
// This round: 8x8 thread tile (4 LDS.128 + 64 FFMA per kk), reg-prefetch
// double buffer, one barrier per chunk. 3x3 convs = 9 shifted 1x1 GEMMs
// over statically-zero padded planes. Full fp32 (rel_err ~1.6e-6).
// ===========================================================================

static constexpr int HH = 129, WW = 129, HWP = HH * WW;   // 16641
static constexpr int PH = 131;                            // padded row width
static constexpr int PHW = PH * PH;                       // 17161
static constexpr int PLANE = 17568;                       // padded plane + guards
static constexpr int GUARD = 132;                         // lead guard
static constexpr int MT = 135;                            // ceil(17161/128)

__device__ float g_up_pad [4 * 128 * PLANE];  // padded upsampled low feats
__device__ float g_red_pad[2 * 512 * PLANE];  // padded relu(conv1) concat
__device__ float g_c2  [2 * 256 * HWP];       // relu(conv2), unpadded
__device__ float g_kern[2 * 49  * HWP];       // softmax kernels
__device__ float g_w1T [9 * 256 * 128];       // w_reduce [tap][oc][ci]
__device__ float g_w2T [9 * 256 * 512];       // w_conv2  [tap][oc][ci]

// ---------------------------------------------------------------------------
// 1) Bilinear upsample into padded layout (pads remain statically-zero)
// ---------------------------------------------------------------------------
__global__ __launch_bounds__(256)
void upsample_kernel(const float* __restrict__ cur, const float* __restrict__ key)
{
    int idx = blockIdx.x * 256 + threadIdx.x;
    if (idx >= 4 * 128 * HWP) return;
    int slot = idx / (128 * HWP);
    int rem  = idx - slot * (128 * HWP);
    int c    = rem / HWP;
    int p    = rem - c * HWP;
    int Y = p / WW, X = p - Y * WW;
    int frame = slot & 1, b = slot >> 1;
    const float* src = (frame ? key : cur) + (b * 128 + c) * (33 * 33);

    const float s = 33.0f / 129.0f;
    float fy = (Y + 0.5f) * s - 0.5f;
    float fx = (X + 0.5f) * s - 0.5f;
    float y0f = floorf(fy), x0f = floorf(fx);
    float wy = fy - y0f, wx = fx - x0f;
    int y0 = (int)y0f, x0 = (int)x0f;
    int y0c = max(y0, 0), y1c = min(y0 + 1, 32);
    int x0c = max(x0, 0), x1c = min(x0 + 1, 32);

    float v00 = src[y0c * 33 + x0c], v01 = src[y0c * 33 + x1c];
    float v10 = src[y1c * 33 + x0c], v11 = src[y1c * 33 + x1c];
    float v0 = v00 + (v01 - v00) * wx;
    float v1 = v10 + (v11 - v10) * wx;
    g_up_pad[(size_t)slot * (128 * PLANE) + (size_t)c * PLANE
             + GUARD + (Y + 1) * PH + (X + 1)] = v0 + (v1 - v0) * wy;
}

// ---------------------------------------------------------------------------
// Weight transpose: wT[tap][oc][ci] = w[oc][ci][tap]
// ---------------------------------------------------------------------------
__global__ __launch_bounds__(256)
void transpose_w_kernel(const float* __restrict__ w, float* __restrict__ wT, int CIN)
{
    int i = blockIdx.x * 256 + threadIdx.x;
    int total = 9 * 256 * CIN;
    if (i >= total) return;
    int tap = i / (256 * CIN);
    int rem = i - tap * (256 * CIN);
    int n   = rem / CIN;
    int ci  = rem - n * CIN;
    wT[i] = w[(n * CIN + ci) * 9 + tap];
}

// ---------------------------------------------------------------------------
// 2/3) 3x3 conv as SIMT fp32 implicit GEMM.
//   CTA: M=128 pixels x N=128 ocs, BK=8, 256 threads (16 tx x 16 tn).
//   Thread tile 8x8: m in {tx*4..+3, 64+tx*4..+3}, n likewise with tn.
//   Per kk: 4 LDS.128 + 64 FFMA. Reg-prefetch + double smem buffer,
//   ONE barrier per chunk (R8-proven pipeline shell).
//   K loop: 9 taps x CIN/8 chunks over shifted padded planes.
//   MODE 0: g_up_pad(128ch, img z)    -> g_red_pad (padded, relu)
//   MODE 1: g_red_pad(512ch, batch z) -> g_c2 (unpadded, relu)
// ---------------------------------------------------------------------------
template<int CIN, int MODE>
__global__ __launch_bounds__(256, 2)
void conv_sgemm(const float* __restrict__ wT, const float* __restrict__ bias)
{
    constexpr int KC    = CIN / 8;      // k-chunks per tap
    constexpr int TOTAL = 9 * KC;

    __shared__ __align__(16) float sA[2][8][128];
    __shared__ __align__(16) float sB[2][8][132];   // 16B-aligned rows

    const int tid = threadIdx.x;
    const int tx  = tid & 15;
    const int tn  = tid >> 4;
    const int Lbase = blockIdx.x * 128;
    const int n0    = blockIdx.y * 128;

    const float* in = (MODE == 0)
        ? (g_up_pad  + (size_t)blockIdx.z * (128 * PLANE))
        : (g_red_pad + (size_t)blockIdx.z * (512 * PLANE));

    // prefetch maps (fixed per thread)
    const int a_kb = tid >> 7;           // k = a_kb + 2*i  (i = 0..3)
    const int a_m  = tid & 127;
    const int b_n  = tid >> 1;           // n = b_n
    const int b_kq = (tid & 1) * 4;      // k = b_kq .. b_kq+3

    float acc[8][8];
#pragma unroll
    for (int i = 0; i < 8; ++i)
#pragma unroll
        for (int j = 0; j < 8; ++j) acc[i][j] = 0.f;

    float ra[4];
    float4 rb;

    // ---- prologue: prefetch chunk 0 (tap 0 => off = -PH-1, c0 = 0) ----
    {
        const float* ag = in + (GUARD - PH - 1) + Lbase + a_m;
#pragma unroll
        for (int i = 0; i < 4; ++i)
            ra[i] = __ldg(ag + (size_t)(a_kb + 2 * i) * PLANE);
        rb = __ldg((const float4*)(wT + (size_t)(n0 + b_n) * CIN + b_kq));
    }

    for (int it = 0; it < TOTAL; ++it) {
        const int buf = it & 1;

        // ---- store prefetched chunk to smem ----
#pragma unroll
        for (int i = 0; i < 4; ++i) sA[buf][a_kb + 2 * i][a_m] = ra[i];
        sB[buf][b_kq + 0][b_n] = rb.x;
        sB[buf][b_kq + 1][b_n] = rb.y;
        sB[buf][b_kq + 2][b_n] = rb.z;
        sB[buf][b_kq + 3][b_n] = rb.w;
        __syncthreads();

        // ---- prefetch next chunk into regs (hidden under compute) ----
        if (it + 1 < TOTAL) {
            const int nit = it + 1;
            const int tap = nit / KC;
            const int c0  = (nit - tap * KC) * 8;
            const int off = (tap / 3 - 1) * PH + (tap % 3 - 1);
            const float* ag = in + (size_t)c0 * PLANE + GUARD + Lbase + off + a_m;
#pragma unroll
            for (int i = 0; i < 4; ++i)
                ra[i] = __ldg(ag + (size_t)(a_kb + 2 * i) * PLANE);
            rb = __ldg((const float4*)
                (wT + ((size_t)tap * 256 + n0 + b_n) * CIN + c0 + b_kq));
        }

        // ---- compute 8 k-steps: 4 LDS.128 + 64 FFMA each ----
#pragma unroll
        for (int kk = 0; kk < 8; ++kk) {
            float a[8], b[8];
            *(float4*)&a[0] = *(const float4*)&sA[buf][kk][tx * 4];
            *(float4*)&a[4] = *(const float4*)&sA[buf][kk][64 + tx * 4];
            *(float4*)&b[0] = *(const float4*)&sB[buf][kk][tn * 4];
            *(float4*)&b[4] = *(const float4*)&sB[buf][kk][64 + tn * 4];
#pragma unroll
            for (int i = 0; i < 8; ++i)
#pragma unroll
                for (int j = 0; j < 8; ++j)
                    acc[i][j] += a[i] * b[j];
        }
    }

    // ---- epilogue: bias + relu, interior-only stores ----
    float bv[8];
#pragma unroll
    for (int j = 0; j < 8; ++j) {
        int n = n0 + (j < 4 ? tn * 4 + j : 64 + tn * 4 + j - 4);
        bv[j] = __ldg(bias + n);
    }

#pragma unroll
    for (int i = 0; i < 8; ++i) {
        const int m = (i < 4 ? tx * 4 + i : 64 + tx * 4 + i - 4);
        const int L = Lbase + m;
        const int r = L / PH, c = L - r * PH;
        const bool valid = (L < PHW) && (r >= 1) && (r <= HH)
                                     && (c >= 1) && (c <= WW);
        if (!valid) continue;
#pragma unroll
        for (int j = 0; j < 8; ++j) {
            const int n = n0 + (j < 4 ? tn * 4 + j : 64 + tn * 4 + j - 4);
            float v = fmaxf(acc[i][j] + bv[j], 0.f);
            if (MODE == 0)
                g_red_pad[((size_t)blockIdx.z * 256 + n) * PLANE + GUARD + L] = v;
            else
                g_c2[((size_t)blockIdx.z * 256 + n) * HWP
                     + (r - 1) * WW + (c - 1)] = v;
        }
    }
}

// ---------------------------------------------------------------------------
// 4) conv3 (1x1, 256->49) + bias + relu + softmax (proven R5 version)
// ---------------------------------------------------------------------------
__global__ __launch_bounds__(256)
void conv3_softmax_kernel(const float* __restrict__ w3, const float* __restrict__ b3)
{
    __shared__ float sw[49 * 128];
    int g = blockIdx.x * 256 + threadIdx.x;
    bool valid = g < 2 * HWP;
    int b = 0, p = 0;
    if (valid) { b = g / HWP; p = g - b * HWP; }

    float acc[49];
#pragma unroll
    for (int t = 0; t < 49; t++) acc[t] = 0.f;

    for (int h = 0; h < 2; h++) {
        __syncthreads();
        for (int e = threadIdx.x; e < 49 * 128; e += 256)
            sw[e] = w3[(e >> 7) * 256 + h * 128 + (e & 127)];
        __syncthreads();
        if (valid) {
            const float* xc = g_c2 + (size_t)b * (256 * HWP) + (size_t)h * 128 * HWP + p;
            for (int cl = 0; cl < 128; cl++) {
                float xv = __ldg(xc + cl * HWP);
#pragma unroll
                for (int t = 0; t < 49; t++)
                    acc[t] += xv * sw[t * 128 + cl];
            }
        }
    }
    if (!valid) return;

    float mx = -1e30f;
#pragma unroll
    for (int t = 0; t < 49; t++) {
        acc[t] = fmaxf(acc[t] + b3[t], 0.f);
        mx = fmaxf(mx, acc[t]);
    }
    float s = 0.f;
#pragma unroll
    for (int t = 0; t < 49; t++) { acc[t] = expf(acc[t] - mx); s += acc[t]; }
    float inv = 1.f / s;
#pragma unroll
    for (int t = 0; t < 49; t++)
        g_kern[((size_t)b * 49 + t) * HWP + p] = acc[t] * inv;
}

// ---------------------------------------------------------------------------
// 5) Spatially-variant 7x7 conv (proven R5 version)
// ---------------------------------------------------------------------------
__global__ __launch_bounds__(256)
void svc_kernel(const float* __restrict__ feat, float* __restrict__ out)
{
    __shared__ float sk[49][128];
    const int x0 = blockIdx.x * 16, y0 = blockIdx.y * 8, b = blockIdx.z;
    const int tid = threadIdx.x;

    for (int e = tid; e < 49 * 128; e += 256) {
        int t = e >> 7, pix = e & 127;
        int yy = y0 + (pix >> 4), xx = x0 + (pix & 15);
        float v = 0.f;
        if (yy < HH && xx < WW) v = g_kern[((size_t)b * 49 + t) * HWP + yy * WW + xx];
        sk[t][pix] = v;
    }
    __syncthreads();

    const int half = tid >> 7;
    const int pix  = tid & 127;
    const int y = y0 + (pix >> 4);
    const int x = x0 + (pix & 15);
    const bool valid = (y < HH) && (x < WW);
    const float* fb = feat + (size_t)b * 256 * HWP;

    for (int c = half; c < 256; c += 2) {
        const float* fc = fb + (size_t)c * HWP;
        float acc = 0.f;
#pragma unroll
        for (int i = 0; i < 7; i++) {
            int yy = y + i - 3;
            if ((unsigned)yy < (unsigned)HH) {
#pragma unroll
                for (int j = 0; j < 7; j++) {
                    int xx = x + j - 3;
                    if ((unsigned)xx < (unsigned)WW)
                        acc += sk[i * 7 + j][pix] * __ldg(fc + yy * WW + xx);
                }
            }
        }
        if (valid) out[((size_t)b * 256 + c) * HWP + y * WW + x] = acc;
    }
}

// ---------------------------------------------------------------------------
// Launcher (graph-capturable: kernel launches only)
// ---------------------------------------------------------------------------
extern "C" void kernel_launch(void* const* d_in, const int* in_sizes, int n_in,
                              void* d_out, int out_size)
{
    const float* cur = (const float*)d_in[0];
    const float* key = (const float*)d_in[1];
    const float* hi  = (const float*)d_in[2];
    const float* w1  = (const float*)d_in[3];
    const float* b1  = (const float*)d_in[4];
    const float* w2  = (const float*)d_in[5];
    const float* b2  = (const float*)d_in[6];
    const float* w3  = (const float*)d_in[7];
    const float* b3  = (const float*)d_in[8];
    float* out = (float*)d_out;

    // weight transposes (tiny) + padded upsample
    transpose_w_kernel<<<(9 * 256 * 128 + 255) / 256, 256>>>(w1, g_w1T, 128);
    transpose_w_kernel<<<(9 * 256 * 512 + 255) / 256, 256>>>(w2, g_w2T, 512);
    upsample_kernel<<<(4 * 128 * HWP + 255) / 256, 256>>>(cur, key);

    // conv_reduce: 4 image slots -> padded concat layout (relu fused)
    conv_sgemm<128, 0><<<dim3(MT, 2, 4), 256>>>(g_w1T, b1);

    // conv2: per batch (relu fused)
    conv_sgemm<512, 1><<<dim3(MT, 2, 2), 256>>>(g_w2T, b2);

    // conv3 + relu + softmax
    conv3_softmax_kernel<<<(2 * HWP + 255) / 256, 256>>>(w3, b3);

    // spatially-variant 7x7 conv
    svc_kernel<<<dim3(9, 17, 2), 256>>>(hi, out);
}

// round 15
// speedup vs baseline: 3.1346x; 1.3774x over previous
#include <cuda_runtime.h>
#include <math.h>
#include <stdint.h>

// ===========================================================================
// AdaptiveFeaturePropagation, round 15: factorized conv1 rebuilt for
// obvious correctness (fault-isolation round).
//   conv1 = sum_tap bilin_sample(Z_tap), Z_tap = 1x1 GEMM on 33x33 grid.
//   Z: simple smem-broadcast kernel (no custom GEMM maps).
//   gather: direct-LDG bilinear, R5-proven clamp math, no smem/no barriers.
//   conv2: R14 SIMT SGEMM (128x64, 4x8 tile, 3 CTAs/SM).
//   conv3+softmax, svc: proven R5 versions.
// ===========================================================================

static constexpr int HH = 129, WW = 129, HWP = HH * WW;   // 16641
static constexpr int PH = 131;                            // padded row width
static constexpr int PHW = PH * PH;                       // 17161
static constexpr int PLANE = 17568;                       // padded plane + guards
static constexpr int GUARD = 132;                         // lead guard
static constexpr int MT = 135;                            // ceil(17161/128)
static constexpr int LHW = 33 * 33;                       // 1089

__device__ float g_z   [4 * 9 * LHW * 256];   // Z[slot*9+tap][px][oc]
__device__ float g_red_pad[2 * 512 * PLANE];  // padded relu(conv1) concat
__device__ float g_c2  [2 * 256 * HWP];       // relu(conv2), unpadded
__device__ float g_kern[2 * 49  * HWP];       // softmax kernels
__device__ float g_w1C [9 * 128 * 256];       // w_reduce as [tap][ci][oc]
__device__ float g_w2T [9 * 256 * 512];       // w_conv2  as [tap][oc][ci]

// ---------------------------------------------------------------------------
// Weight transposes
// ---------------------------------------------------------------------------
__global__ __launch_bounds__(256)
void transpose_w1c_kernel(const float* __restrict__ w)   // -> [tap][ci][oc]
{
    int i = blockIdx.x * 256 + threadIdx.x;
    if (i >= 9 * 128 * 256) return;
    int tap = i / (128 * 256);
    int rem = i - tap * (128 * 256);
    int ci  = rem >> 8;
    int oc  = rem & 255;
    g_w1C[i] = w[((size_t)oc * 128 + ci) * 9 + tap];
}

__global__ __launch_bounds__(256)
void transpose_w_kernel(const float* __restrict__ w, float* __restrict__ wT, int CIN)
{
    int i = blockIdx.x * 256 + threadIdx.x;
    int total = 9 * 256 * CIN;
    if (i >= total) return;
    int tap = i / (256 * CIN);
    int rem = i - tap * (256 * CIN);
    int n   = rem / CIN;
    int ci  = rem - n * CIN;
    wT[i] = w[(n * CIN + ci) * 9 + tap];
}

// ---------------------------------------------------------------------------
// Z kernel (simple, correct-by-construction):
//   Z[z][px][oc] = sum_ci w1[oc][ci][tap] * x_s[ci][px],  z = s*9 + tap
//   Block: one (z, 4-pixel group); 256 threads = 256 ocs.
//   x staged [ci][4] in smem (LDS.128 broadcast); w read coalesced 1024B/ci.
// ---------------------------------------------------------------------------
__global__ __launch_bounds__(256)
void zlow_simple(const float* __restrict__ cur, const float* __restrict__ key)
{
    __shared__ __align__(16) float sx[128][4];
    const int tid = threadIdx.x;
    const int px4 = blockIdx.x * 4;
    const int z   = blockIdx.z;
    const int s   = z / 9, tap = z - s * 9;
    const int frame = s & 1, b = s >> 1;

    const float* in = (frame ? key : cur) + (size_t)b * 128 * LHW;
    const float* wc = g_w1C + (size_t)tap * 128 * 256;

    for (int e = tid; e < 512; e += 256) {
        int ci = e >> 2, p = e & 3;
        int px = px4 + p;
        sx[ci][p] = (px < LHW) ? __ldg(in + (size_t)ci * LHW + px) : 0.f;
    }
    __syncthreads();

    float a0 = 0.f, a1 = 0.f, a2 = 0.f, a3 = 0.f;
#pragma unroll 4
    for (int ci = 0; ci < 128; ++ci) {
        float w = __ldg(wc + ci * 256 + tid);
        float4 xv = *(const float4*)sx[ci];
        a0 += w * xv.x; a1 += w * xv.y; a2 += w * xv.z; a3 += w * xv.w;
    }

    float* zp = g_z + (size_t)z * LHW * 256;
    if (px4 + 0 < LHW) zp[(size_t)(px4 + 0) * 256 + tid] = a0;
    if (px4 + 1 < LHW) zp[(size_t)(px4 + 1) * 256 + tid] = a1;
    if (px4 + 2 < LHW) zp[(size_t)(px4 + 2) * 256 + tid] = a2;
    if (px4 + 3 < LHW) zp[(size_t)(px4 + 3) * 256 + tid] = a3;
}

// ---------------------------------------------------------------------------
// Gather: conv1 = relu(b1 + sum_tap bilin(Z_tap at (Y+dy-1, X+dx-1))),
//   written to padded concat layout g_red_pad. Direct LDG, no smem.
//   Thread = one pixel x 32 ocs; grid (9, 9, 4 slots * 8 ocblk).
//   Bilinear clamp math identical to the R5-proven upsample kernel.
// ---------------------------------------------------------------------------
__global__ __launch_bounds__(256)
void gather_conv1(const float* __restrict__ b1)
{
    const int x0 = blockIdx.x * 16, y0 = blockIdx.y * 16;
    const int s  = blockIdx.z >> 3;
    const int c0 = (blockIdx.z & 7) * 32;
    const int tid = threadIdx.x;
    const int x = x0 + (tid & 15);
    const int y = y0 + (tid >> 4);
    if (x > 128 || y > 128) return;

    const float S = 33.0f / 129.0f;
    float acc[32];
#pragma unroll
    for (int o = 0; o < 32; ++o) acc[o] = 0.f;

    const float* Zs = g_z + (size_t)s * 9 * LHW * 256 + c0;

#pragma unroll
    for (int tap = 0; tap < 9; ++tap) {
        const int dy = tap / 3, dx = tap - dy * 3;
        const int Yp = y + dy - 1, Xp = x + dx - 1;
        if ((unsigned)Yp > 128u || (unsigned)Xp > 128u) continue;   // conv zero-pad

        const float fy = (Yp + 0.5f) * S - 0.5f;
        const float fx = (Xp + 0.5f) * S - 0.5f;
        const float y0f = floorf(fy), x0f = floorf(fx);
        const float wy = fy - y0f, wx = fx - x0f;
        const int iy = (int)y0f, ix = (int)x0f;
        const int y0c = max(iy, 0),     y1c = min(iy + 1, 32);
        const int x0c = max(ix, 0),     x1c = min(ix + 1, 32);
        const float w00 = (1.f - wy) * (1.f - wx), w01 = (1.f - wy) * wx;
        const float w10 = wy * (1.f - wx),         w11 = wy * wx;

        const float* zp = Zs + (size_t)tap * LHW * 256;
        const float4* p00 = (const float4*)(zp + (size_t)(y0c * 33 + x0c) * 256);
        const float4* p01 = (const float4*)(zp + (size_t)(y0c * 33 + x1c) * 256);
        const float4* p10 = (const float4*)(zp + (size_t)(y1c * 33 + x0c) * 256);
        const float4* p11 = (const float4*)(zp + (size_t)(y1c * 33 + x1c) * 256);

#pragma unroll
        for (int og = 0; og < 8; ++og) {
            float4 v00 = __ldg(p00 + og);
            float4 v01 = __ldg(p01 + og);
            float4 v10 = __ldg(p10 + og);
            float4 v11 = __ldg(p11 + og);
            acc[og * 4 + 0] += w00 * v00.x + w01 * v01.x + w10 * v10.x + w11 * v11.x;
            acc[og * 4 + 1] += w00 * v00.y + w01 * v01.y + w10 * v10.y + w11 * v11.y;
            acc[og * 4 + 2] += w00 * v00.z + w01 * v01.z + w10 * v10.z + w11 * v11.z;
            acc[og * 4 + 3] += w00 * v00.w + w01 * v01.w + w10 * v10.w + w11 * v11.w;
        }
    }

    // channel = s*256 + c0 + o  (concat layout: slot s = 2*b + frame)
    const size_t base = ((size_t)s * 256 + c0) * PLANE
                      + GUARD + (size_t)(y + 1) * PH + (x + 1);
#pragma unroll
    for (int o = 0; o < 32; ++o)
        g_red_pad[base + (size_t)o * PLANE]
            = fmaxf(acc[o] + __ldg(b1 + c0 + o), 0.f);
}

// ---------------------------------------------------------------------------
// conv2 (3x3, 512->256) as SIMT SGEMM over 9 shifted padded planes.
//   CTA 128(M) x 64(N), 256 thr (32 tx x 8 tn), thread tile 4x8.
//   BK=8; reg-prefetch + double smem buffer; 576 chunks.  (R14 version)
// ---------------------------------------------------------------------------
__global__ __launch_bounds__(256, 3)
void conv2_sgemm(const float* __restrict__ wT, const float* __restrict__ bias)
{
    constexpr int CIN = 512;
    constexpr int KC = CIN / 8;          // 64
    constexpr int TOTAL = 9 * KC;        // 576

    __shared__ __align__(16) float sA[2][8][128];
    __shared__ __align__(16) float sB[2][8][68];

    const int tid = threadIdx.x;
    const int tx  = tid & 31;
    const int tn  = tid >> 5;
    const int Lbase = blockIdx.x * 128;
    const int n0    = blockIdx.y * 64;

    const float* in = g_red_pad + (size_t)blockIdx.z * (512 * PLANE);

    const int a_kb = tid >> 7;
    const int a_m  = tid & 127;
    const int b_n  = tid >> 2;
    const int b_k  = (tid & 3) * 2;

    float acc[4][8];
#pragma unroll
    for (int i = 0; i < 4; ++i)
#pragma unroll
        for (int j = 0; j < 8; ++j) acc[i][j] = 0.f;

    float ra[4]; float2 rb;
    {   // chunk 0: tap 0 => off = -PH-1, c0 = 0
        const float* ag = in + (GUARD - PH - 1) + Lbase + a_m;
#pragma unroll
        for (int i = 0; i < 4; ++i)
            ra[i] = __ldg(ag + (size_t)(a_kb + 2 * i) * PLANE);
        rb = __ldg((const float2*)(wT + (size_t)(n0 + b_n) * CIN + b_k));
    }

    for (int it = 0; it < TOTAL; ++it) {
        const int buf = it & 1;
#pragma unroll
        for (int i = 0; i < 4; ++i) sA[buf][a_kb + 2 * i][a_m] = ra[i];
        sB[buf][b_k][b_n] = rb.x;
        sB[buf][b_k + 1][b_n] = rb.y;
        __syncthreads();

        if (it + 1 < TOTAL) {
            const int nit = it + 1;
            const int tap = nit / KC;
            const int c0  = (nit - tap * KC) * 8;
            const int off = (tap / 3 - 1) * PH + (tap % 3 - 1);
            const float* ag = in + (size_t)c0 * PLANE + GUARD + Lbase + off + a_m;
#pragma unroll
            for (int i = 0; i < 4; ++i)
                ra[i] = __ldg(ag + (size_t)(a_kb + 2 * i) * PLANE);
            rb = __ldg((const float2*)
                (wT + ((size_t)tap * 256 + n0 + b_n) * CIN + c0 + b_k));
        }

#pragma unroll
        for (int kk = 0; kk < 8; ++kk) {
            float a[4], bb[8];
            *(float4*)&a[0]  = *(const float4*)&sA[buf][kk][tx * 4];
            *(float4*)&bb[0] = *(const float4*)&sB[buf][kk][tn * 4];
            *(float4*)&bb[4] = *(const float4*)&sB[buf][kk][32 + tn * 4];
#pragma unroll
            for (int i = 0; i < 4; ++i)
#pragma unroll
                for (int j = 0; j < 8; ++j)
                    acc[i][j] += a[i] * bb[j];
        }
        __syncthreads();
    }

    float bv[8];
#pragma unroll
    for (int j = 0; j < 8; ++j)
        bv[j] = __ldg(bias + n0 + (j < 4 ? tn * 4 + j : 32 + tn * 4 + j - 4));

#pragma unroll
    for (int i = 0; i < 4; ++i) {
        const int L = Lbase + tx * 4 + i;
        const int r = L / PH, c = L - r * PH;
        const bool valid = (L < PHW) && (r >= 1) && (r <= HH)
                                     && (c >= 1) && (c <= WW);
        if (!valid) continue;
#pragma unroll
        for (int j = 0; j < 8; ++j) {
            const int n = n0 + (j < 4 ? tn * 4 + j : 32 + tn * 4 + j - 4);
            g_c2[((size_t)blockIdx.z * 256 + n) * HWP + (r - 1) * WW + (c - 1)]
                = fmaxf(acc[i][j] + bv[j], 0.f);
        }
    }
}

// ---------------------------------------------------------------------------
// conv3 (1x1, 256->49) + bias + relu + softmax (proven R5 version)
// ---------------------------------------------------------------------------
__global__ __launch_bounds__(256)
void conv3_softmax_kernel(const float* __restrict__ w3, const float* __restrict__ b3)
{
    __shared__ float sw[49 * 128];
    int g = blockIdx.x * 256 + threadIdx.x;
    bool valid = g < 2 * HWP;
    int b = 0, p = 0;
    if (valid) { b = g / HWP; p = g - b * HWP; }

    float acc[49];
#pragma unroll
    for (int t = 0; t < 49; t++) acc[t] = 0.f;

    for (int h = 0; h < 2; h++) {
        __syncthreads();
        for (int e = threadIdx.x; e < 49 * 128; e += 256)
            sw[e] = w3[(e >> 7) * 256 + h * 128 + (e & 127)];
        __syncthreads();
        if (valid) {
            const float* xc = g_c2 + (size_t)b * (256 * HWP) + (size_t)h * 128 * HWP + p;
            for (int cl = 0; cl < 128; cl++) {
                float xv = __ldg(xc + cl * HWP);
#pragma unroll
                for (int t = 0; t < 49; t++)
                    acc[t] += xv * sw[t * 128 + cl];
            }
        }
    }
    if (!valid) return;

    float mx = -1e30f;
#pragma unroll
    for (int t = 0; t < 49; t++) {
        acc[t] = fmaxf(acc[t] + b3[t], 0.f);
        mx = fmaxf(mx, acc[t]);
    }
    float s = 0.f;
#pragma unroll
    for (int t = 0; t < 49; t++) { acc[t] = expf(acc[t] - mx); s += acc[t]; }
    float inv = 1.f / s;
#pragma unroll
    for (int t = 0; t < 49; t++)
        g_kern[((size_t)b * 49 + t) * HWP + p] = acc[t] * inv;
}

// ---------------------------------------------------------------------------
// Spatially-variant 7x7 conv (proven R5 version)
// ---------------------------------------------------------------------------
__global__ __launch_bounds__(256)
void svc_kernel(const float* __restrict__ feat, float* __restrict__ out)
{
    __shared__ float sk[49][128];
    const int x0 = blockIdx.x * 16, y0 = blockIdx.y * 8, b = blockIdx.z;
    const int tid = threadIdx.x;

    for (int e = tid; e < 49 * 128; e += 256) {
        int t = e >> 7, pix = e & 127;
        int yy = y0 + (pix >> 4), xx = x0 + (pix & 15);
        float v = 0.f;
        if (yy < HH && xx < WW) v = g_kern[((size_t)b * 49 + t) * HWP + yy * WW + xx];
        sk[t][pix] = v;
    }
    __syncthreads();

    const int half = tid >> 7;
    const int pix  = tid & 127;
    const int y = y0 + (pix >> 4);
    const int x = x0 + (pix & 15);
    const bool valid = (y < HH) && (x < WW);
    const float* fb = feat + (size_t)b * 256 * HWP;

    for (int c = half; c < 256; c += 2) {
        const float* fc = fb + (size_t)c * HWP;
        float acc = 0.f;
#pragma unroll
        for (int i = 0; i < 7; i++) {
            int yy = y + i - 3;
            if ((unsigned)yy < (unsigned)HH) {
#pragma unroll
                for (int j = 0; j < 7; j++) {
                    int xx = x + j - 3;
                    if ((unsigned)xx < (unsigned)WW)
                        acc += sk[i * 7 + j][pix] * __ldg(fc + yy * WW + xx);
                }
            }
        }
        if (valid) out[((size_t)b * 256 + c) * HWP + y * WW + x] = acc;
    }
}

// ---------------------------------------------------------------------------
// Launcher (graph-capturable: kernel launches only)
// ---------------------------------------------------------------------------
extern "C" void kernel_launch(void* const* d_in, const int* in_sizes, int n_in,
                              void* d_out, int out_size)
{
    const float* cur = (const float*)d_in[0];
    const float* key = (const float*)d_in[1];
    const float* hi  = (const float*)d_in[2];
    const float* w1  = (const float*)d_in[3];
    const float* b1  = (const float*)d_in[4];
    const float* w2  = (const float*)d_in[5];
    const float* b2  = (const float*)d_in[6];
    const float* w3  = (const float*)d_in[7];
    const float* b3  = (const float*)d_in[8];
    float* out = (float*)d_out;

    // weight transposes (tiny)
    transpose_w1c_kernel<<<(9 * 128 * 256 + 255) / 256, 256>>>(w1);
    transpose_w_kernel<<<(9 * 256 * 512 + 255) / 256, 256>>>(w2, g_w2T, 512);

    // conv1 factorized: simple Z kernel, then direct-LDG bilinear gather
    zlow_simple<<<dim3((LHW + 3) / 4, 1, 36), 256>>>(cur, key);
    gather_conv1<<<dim3(9, 9, 32), 256>>>(b1);

    // conv2: per batch (relu fused)
    conv2_sgemm<<<dim3(MT, 4, 2), 256>>>(g_w2T, b2);

    // conv3 + relu + softmax
    conv3_softmax_kernel<<<(2 * HWP + 255) / 256, 256>>>(w3, b3);

    // spatially-variant 7x7 conv
    svc_kernel<<<dim3(9, 17, 2), 256>>>(hi, out);
}

// round 17
// speedup vs baseline: 4.6463x; 1.4823x over previous
#include <cuda_runtime.h>
#include <math.h>
#include <stdint.h>

// ===========================================================================
// AdaptiveFeaturePropagation, round 17: verified-pieces-only build.
//   conv1 = sum_tap bilin_sample(Z_tap), Z_tap = 1x1 GEMM on 33x33 grid
//           (R15-verified zlow_simple + gather_conv1; gather now writes the
//            UNPADDED g_red concat buffer - one-line index change)
//   conv2 = R5's runtime-proven conv_igemm<512,1>, VERBATIM (im2col on the
//           fly, original w2 layout, unpadded g_red input)
//   conv3+softmax, svc: proven R5 versions.
// ===========================================================================

static constexpr int HH = 129, WW = 129, HWP = HH * WW;   // 16641
static constexpr int LHW = 33 * 33;                       // 1089

__device__ float g_z   [4 * 9 * LHW * 256];   // Z[slot*9+tap][px][oc]
__device__ float g_red [2 * 512 * HWP];       // relu(conv1) concat, unpadded
__device__ float g_c2  [2 * 256 * HWP];       // relu(conv2), unpadded
__device__ float g_kern[2 * 49  * HWP];       // softmax kernels
__device__ float g_w1C [9 * 128 * 256];       // w_reduce as [tap][ci][oc]

// ---------------------------------------------------------------------------
// Weight transpose for conv1 -> [tap][ci][oc]  (R15-verified)
// ---------------------------------------------------------------------------
__global__ __launch_bounds__(256)
void transpose_w1c_kernel(const float* __restrict__ w)
{
    int i = blockIdx.x * 256 + threadIdx.x;
    if (i >= 9 * 128 * 256) return;
    int tap = i / (128 * 256);
    int rem = i - tap * (128 * 256);
    int ci  = rem >> 8;
    int oc  = rem & 255;
    g_w1C[i] = w[((size_t)oc * 128 + ci) * 9 + tap];
}

// ---------------------------------------------------------------------------
// Z kernel (R15-verified): Z[z][px][oc] = sum_ci w1[oc][ci][tap] * x_s[ci][px]
// ---------------------------------------------------------------------------
__global__ __launch_bounds__(256)
void zlow_simple(const float* __restrict__ cur, const float* __restrict__ key)
{
    __shared__ __align__(16) float sx[128][4];
    const int tid = threadIdx.x;
    const int px4 = blockIdx.x * 4;
    const int z   = blockIdx.z;
    const int s   = z / 9, tap = z - s * 9;
    const int frame = s & 1, b = s >> 1;

    const float* in = (frame ? key : cur) + (size_t)b * 128 * LHW;
    const float* wc = g_w1C + (size_t)tap * 128 * 256;

    for (int e = tid; e < 512; e += 256) {
        int ci = e >> 2, p = e & 3;
        int px = px4 + p;
        sx[ci][p] = (px < LHW) ? __ldg(in + (size_t)ci * LHW + px) : 0.f;
    }
    __syncthreads();

    float a0 = 0.f, a1 = 0.f, a2 = 0.f, a3 = 0.f;
#pragma unroll 4
    for (int ci = 0; ci < 128; ++ci) {
        float w = __ldg(wc + ci * 256 + tid);
        float4 xv = *(const float4*)sx[ci];
        a0 += w * xv.x; a1 += w * xv.y; a2 += w * xv.z; a3 += w * xv.w;
    }

    float* zp = g_z + (size_t)z * LHW * 256;
    if (px4 + 0 < LHW) zp[(size_t)(px4 + 0) * 256 + tid] = a0;
    if (px4 + 1 < LHW) zp[(size_t)(px4 + 1) * 256 + tid] = a1;
    if (px4 + 2 < LHW) zp[(size_t)(px4 + 2) * 256 + tid] = a2;
    if (px4 + 3 < LHW) zp[(size_t)(px4 + 3) * 256 + tid] = a3;
}

// ---------------------------------------------------------------------------
// Gather (R15-verified math): conv1 = relu(b1 + sum_tap bilin(Z_tap)).
// Only change vs R15: final store goes to UNPADDED g_red concat layout.
// ---------------------------------------------------------------------------
__global__ __launch_bounds__(256)
void gather_conv1(const float* __restrict__ b1)
{
    const int x0 = blockIdx.x * 16, y0 = blockIdx.y * 16;
    const int s  = blockIdx.z >> 3;
    const int c0 = (blockIdx.z & 7) * 32;
    const int tid = threadIdx.x;
    const int x = x0 + (tid & 15);
    const int y = y0 + (tid >> 4);
    if (x > 128 || y > 128) return;

    const float S = 33.0f / 129.0f;
    float acc[32];
#pragma unroll
    for (int o = 0; o < 32; ++o) acc[o] = 0.f;

    const float* Zs = g_z + (size_t)s * 9 * LHW * 256 + c0;

#pragma unroll
    for (int tap = 0; tap < 9; ++tap) {
        const int dy = tap / 3, dx = tap - dy * 3;
        const int Yp = y + dy - 1, Xp = x + dx - 1;
        if ((unsigned)Yp > 128u || (unsigned)Xp > 128u) continue;   // conv zero-pad

        const float fy = (Yp + 0.5f) * S - 0.5f;
        const float fx = (Xp + 0.5f) * S - 0.5f;
        const float y0f = floorf(fy), x0f = floorf(fx);
        const float wy = fy - y0f, wx = fx - x0f;
        const int iy = (int)y0f, ix = (int)x0f;
        const int y0c = max(iy, 0),     y1c = min(iy + 1, 32);
        const int x0c = max(ix, 0),     x1c = min(ix + 1, 32);
        const float w00 = (1.f - wy) * (1.f - wx), w01 = (1.f - wy) * wx;
        const float w10 = wy * (1.f - wx),         w11 = wy * wx;

        const float* zp = Zs + (size_t)tap * LHW * 256;
        const float4* p00 = (const float4*)(zp + (size_t)(y0c * 33 + x0c) * 256);
        const float4* p01 = (const float4*)(zp + (size_t)(y0c * 33 + x1c) * 256);
        const float4* p10 = (const float4*)(zp + (size_t)(y1c * 33 + x0c) * 256);
        const float4* p11 = (const float4*)(zp + (size_t)(y1c * 33 + x1c) * 256);

#pragma unroll
        for (int og = 0; og < 8; ++og) {
            float4 v00 = __ldg(p00 + og);
            float4 v01 = __ldg(p01 + og);
            float4 v10 = __ldg(p10 + og);
            float4 v11 = __ldg(p11 + og);
            acc[og * 4 + 0] += w00 * v00.x + w01 * v01.x + w10 * v10.x + w11 * v11.x;
            acc[og * 4 + 1] += w00 * v00.y + w01 * v01.y + w10 * v10.y + w11 * v11.y;
            acc[og * 4 + 2] += w00 * v00.z + w01 * v01.z + w10 * v10.z + w11 * v11.z;
            acc[og * 4 + 3] += w00 * v00.w + w01 * v01.w + w10 * v10.w + w11 * v11.w;
        }
    }

    // channel = s*256 + c0 + o == b*512 + frame*256 + c0 + o (concat layout)
    const size_t base = ((size_t)s * 256 + c0) * HWP + (size_t)y * WW + x;
#pragma unroll
    for (int o = 0; o < 32; ++o)
        g_red[base + (size_t)o * HWP]
            = fmaxf(acc[o] + __ldg(b1 + c0 + o), 0.f);
}

// ---------------------------------------------------------------------------
// conv2 (3x3, 512->256): R5's runtime-proven conv_igemm<512,1>, VERBATIM.
//   M = HWP pixels, N = 256 oc, K = 512*9. Block tile 128x64, BK=8,
//   256 threads, 8x4 strided fragments, im2col on the fly, original w2
//   layout [OC][CIN][3][3]. ReLU fused.
// ---------------------------------------------------------------------------
__global__ __launch_bounds__(256)
void conv2_igemm(const float* __restrict__ w, const float* __restrict__ bias)
{
    constexpr int CIN  = 512;
    constexpr int Kdim = CIN * 9;
    __shared__ float As[8][128];
    __shared__ float Bs[8][64];

    const int m0 = blockIdx.x * 128;
    const int n0 = blockIdx.y * 64;

    const float* inImg  = g_red + (size_t)blockIdx.z * (512 * HWP);
    float*       outImg = g_c2  + (size_t)blockIdx.z * (256 * HWP);

    const int tid  = threadIdx.x;
    const int tcol = tid & 15;   // m-dimension lane (16)
    const int trow = tid >> 4;   // n-dimension lane (16)

    float acc[8][4];
#pragma unroll
    for (int i = 0; i < 8; i++)
#pragma unroll
        for (int j = 0; j < 4; j++) acc[i][j] = 0.f;

    for (int k0 = 0; k0 < Kdim; k0 += 8) {
        // --- load A tile (128 x 8, im2col on the fly) ---
#pragma unroll
        for (int r = 0; r < 4; r++) {
            int e  = tid + r * 256;
            int kl = e >> 7, ml = e & 127;
            int m  = m0 + ml;
            int k  = k0 + kl;
            float v = 0.f;
            if (m < HWP) {
                int ci = k / 9;
                int t  = k - ci * 9;
                int ky = t / 3;
                int kx = t - ky * 3;
                int yy = m / WW;
                int xx = m - yy * WW;
                yy += ky - 1;
                xx += kx - 1;
                if ((unsigned)yy < (unsigned)HH && (unsigned)xx < (unsigned)WW)
                    v = __ldg(inImg + ci * HWP + yy * WW + xx);
            }
            As[kl][ml] = v;
        }
        // --- load B tile (8 x 64): B[k][n] = w[n*Kdim + k] ---
#pragma unroll
        for (int r = 0; r < 2; r++) {
            int e  = tid + r * 256;
            int kl = e >> 6, nl = e & 63;
            Bs[kl][nl] = __ldg(w + (n0 + nl) * Kdim + k0 + kl);
        }
        __syncthreads();

#pragma unroll
        for (int kk = 0; kk < 8; kk++) {
            float a[8], bb[4];
#pragma unroll
            for (int i = 0; i < 8; i++) a[i] = As[kk][tcol + i * 16];
#pragma unroll
            for (int j = 0; j < 4; j++) bb[j] = Bs[kk][trow + j * 16];
#pragma unroll
            for (int i = 0; i < 8; i++)
#pragma unroll
                for (int j = 0; j < 4; j++)
                    acc[i][j] += a[i] * bb[j];
        }
        __syncthreads();
    }

    // epilogue: bias + relu, coalesced (16 consecutive pixels per (trow,j,i))
#pragma unroll
    for (int j = 0; j < 4; j++) {
        int n = n0 + trow + j * 16;
        float bv = bias[n];
#pragma unroll
        for (int i = 0; i < 8; i++) {
            int m = m0 + tcol + i * 16;
            if (m < HWP)
                outImg[n * HWP + m] = fmaxf(acc[i][j] + bv, 0.f);
        }
    }
}

// ---------------------------------------------------------------------------
// conv3 (1x1, 256->49) + bias + relu + softmax (proven R5 version)
// ---------------------------------------------------------------------------
__global__ __launch_bounds__(256)
void conv3_softmax_kernel(const float* __restrict__ w3, const float* __restrict__ b3)
{
    __shared__ float sw[49 * 128];
    int g = blockIdx.x * 256 + threadIdx.x;
    bool valid = g < 2 * HWP;
    int b = 0, p = 0;
    if (valid) { b = g / HWP; p = g - b * HWP; }

    float acc[49];
#pragma unroll
    for (int t = 0; t < 49; t++) acc[t] = 0.f;

    for (int h = 0; h < 2; h++) {
        __syncthreads();
        for (int e = threadIdx.x; e < 49 * 128; e += 256)
            sw[e] = w3[(e >> 7) * 256 + h * 128 + (e & 127)];
        __syncthreads();
        if (valid) {
            const float* xc = g_c2 + (size_t)b * (256 * HWP) + (size_t)h * 128 * HWP + p;
            for (int cl = 0; cl < 128; cl++) {
                float xv = __ldg(xc + cl * HWP);
#pragma unroll
                for (int t = 0; t < 49; t++)
                    acc[t] += xv * sw[t * 128 + cl];
            }
        }
    }
    if (!valid) return;

    float mx = -1e30f;
#pragma unroll
    for (int t = 0; t < 49; t++) {
        acc[t] = fmaxf(acc[t] + b3[t], 0.f);
        mx = fmaxf(mx, acc[t]);
    }
    float s = 0.f;
#pragma unroll
    for (int t = 0; t < 49; t++) { acc[t] = expf(acc[t] - mx); s += acc[t]; }
    float inv = 1.f / s;
#pragma unroll
    for (int t = 0; t < 49; t++)
        g_kern[((size_t)b * 49 + t) * HWP + p] = acc[t] * inv;
}

// ---------------------------------------------------------------------------
// Spatially-variant 7x7 conv (proven R5 version)
// ---------------------------------------------------------------------------
__global__ __launch_bounds__(256)
void svc_kernel(const float* __restrict__ feat, float* __restrict__ out)
{
    __shared__ float sk[49][128];
    const int x0 = blockIdx.x * 16, y0 = blockIdx.y * 8, b = blockIdx.z;
    const int tid = threadIdx.x;

    for (int e = tid; e < 49 * 128; e += 256) {
        int t = e >> 7, pix = e & 127;
        int yy = y0 + (pix >> 4), xx = x0 + (pix & 15);
        float v = 0.f;
        if (yy < HH && xx < WW) v = g_kern[((size_t)b * 49 + t) * HWP + yy * WW + xx];
        sk[t][pix] = v;
    }
    __syncthreads();

    const int half = tid >> 7;
    const int pix  = tid & 127;
    const int y = y0 + (pix >> 4);
    const int x = x0 + (pix & 15);
    const bool valid = (y < HH) && (x < WW);
    const float* fb = feat + (size_t)b * 256 * HWP;

    for (int c = half; c < 256; c += 2) {
        const float* fc = fb + (size_t)c * HWP;
        float acc = 0.f;
#pragma unroll
        for (int i = 0; i < 7; i++) {
            int yy = y + i - 3;
            if ((unsigned)yy < (unsigned)HH) {
#pragma unroll
                for (int j = 0; j < 7; j++) {
                    int xx = x + j - 3;
                    if ((unsigned)xx < (unsigned)WW)
                        acc += sk[i * 7 + j][pix] * __ldg(fc + yy * WW + xx);
                }
            }
        }
        if (valid) out[((size_t)b * 256 + c) * HWP + y * WW + x] = acc;
    }
}

// ---------------------------------------------------------------------------
// Launcher (graph-capturable: kernel launches only)
// ---------------------------------------------------------------------------
extern "C" void kernel_launch(void* const* d_in, const int* in_sizes, int n_in,
                              void* d_out, int out_size)
{
    const float* cur = (const float*)d_in[0];
    const float* key = (const float*)d_in[1];
    const float* hi  = (const float*)d_in[2];
    const float* w1  = (const float*)d_in[3];
    const float* b1  = (const float*)d_in[4];
    const float* w2  = (const float*)d_in[5];
    const float* b2  = (const float*)d_in[6];
    const float* w3  = (const float*)d_in[7];
    const float* b3  = (const float*)d_in[8];
    float* out = (float*)d_out;

    // conv1 weight transpose (tiny) -> [tap][ci][oc]
    transpose_w1c_kernel<<<(9 * 128 * 256 + 255) / 256, 256>>>(w1);

    // conv1 factorized: simple Z kernel, then direct-LDG bilinear gather
    zlow_simple<<<dim3((LHW + 3) / 4, 1, 36), 256>>>(cur, key);
    gather_conv1<<<dim3(9, 9, 32), 256>>>(b1);

    // conv2: R5-proven engine, per batch (relu fused), original w2 layout
    conv2_igemm<<<dim3((HWP + 127) / 128, 4, 2), 256>>>(w2, b2);

    // conv3 + relu + softmax
    conv3_softmax_kernel<<<(2 * HWP + 255) / 256, 256>>>(w3, b3);

    // spatially-variant 7x7 conv
    svc_kernel<<<dim3(9, 17, 2), 256>>>(hi, out);
}